// round 11
// baseline (speedup 1.0000x reference)
#include <cuda_runtime.h>
#include <cstdint>

#define EMBED 1024
#define BATCH 4
#define SEQ   2048

// ---- scratch (__device__ globals; no cudaMalloc allowed) ----
__device__ float g_qkv[(size_t)BATCH * SEQ * 3 * EMBED];   // ~100 MB
__device__ float g_att[(size_t)BATCH * SEQ * SEQ];         // ~67 MB
__device__ float g_ctx[(size_t)BATCH * SEQ * EMBED];       // ~33 MB
__device__ float g_vt [(size_t)BATCH * EMBED * SEQ];       // ~33 MB  V transposed

// ================= helpers =================
__device__ __forceinline__ void cp_async16(uint32_t smem, const void* gmem) {
    asm volatile("cp.async.cg.shared.global [%0], [%1], 16;" :: "r"(smem), "l"(gmem) : "memory");
}
__device__ __forceinline__ uint32_t smem_u32(const void* p) {
    uint32_t a;
    asm("{ .reg .u64 t; cvta.to.shared.u64 t, %1; cvt.u32.u64 %0, t; }" : "=r"(a) : "l"(p));
    return a;
}
#define CP_COMMIT() asm volatile("cp.async.commit_group;" ::: "memory")
#define CP_WAIT(n)  asm volatile("cp.async.wait_group %0;" :: "n"(n) : "memory")

// Round-to-nearest-even fp32 -> tf32 via integer ops (cvt.rna.tf32 is broken on
// this toolchain). Unbiased rounding: error ~sqrt(K)*2^-12 (validated: 6.5e-4
// end-to-end vs 4.6e-3 with truncation).
__device__ __forceinline__ uint32_t f2tf32(float x) {
    uint32_t u = __float_as_uint(x);
    return (u + 0xFFFu + ((u >> 13) & 1u)) & 0xFFFFE000u;
}

// m16n8k8 tf32 mma: D = A*B + D. A row-major(16x8), B col-major(8x8).
#define MMA_TF32(c, a, b)                                                     \
    asm volatile(                                                             \
        "mma.sync.aligned.m16n8k8.row.col.f32.tf32.tf32.f32 "                 \
        "{%0,%1,%2,%3}, {%4,%5,%6,%7}, {%8,%9}, {%0,%1,%2,%3};"               \
        : "+f"((c)[0]), "+f"((c)[1]), "+f"((c)[2]), "+f"((c)[3])              \
        : "r"((a)[0]), "r"((a)[1]), "r"((a)[2]), "r"((a)[3]),                 \
          "r"((b)[0]), "r"((b)[1]))

// ================= tf32 mma.sync NT GEMM (fine tiles) =================
// C[m][n] = alpha * sum_k A[m][k]*B[n][k] (+ bias[n]).  A,B K-major fp32.
// BM=64, BN=64, BK=32; 4 warps as 2(m)x2(n) -> 32x32 per warp.
// Fine tiles + ~6 CTAs/SM kill the wave-quantization tail that dominated the
// 128x128 version (~150us). LDS frag pattern (4g+tg) mod 32 is conflict-free.
static constexpr int BM = 64, BN = 64, BK = 32;
static constexpr int LDP = 36;                       // padded row stride (floats)
static constexpr int STAGE_F = 128 * LDP;            // A(64 rows)+B(64 rows) per stage
static constexpr int GEMM_DSMEM = 2 * STAGE_F * 4;   // 36864 bytes

__global__ __launch_bounds__(128, 6) void gemm_mma(
    const float* __restrict__ A, const float* __restrict__ B,
    const float* __restrict__ bias, float* __restrict__ C,
    int K, int lda, int ldb, int ldc,
    long long sA, long long sB, long long sC, float alpha)
{
    extern __shared__ float smem[];

    const int tid = threadIdx.x;
    const int wid = tid >> 5;
    const int lid = tid & 31;
    const int g   = lid >> 2;     // 0..7
    const int tg  = lid & 3;      // 0..3
    const int warp_m = wid >> 1;  // 0..1  -> 32 rows each
    const int warp_n = wid & 1;   // 0..1  -> 32 cols each

    const int bm = blockIdx.y * BM;
    const int bn = blockIdx.x * BN;

    A += blockIdx.z * sA + (long long)bm * lda;
    B += blockIdx.z * sB + (long long)bn * ldb;
    C += blockIdx.z * sC;

    const uint32_t sbase = smem_u32(smem);
    const int NC = K / BK;

    float acc[2][4][4];
    #pragma unroll
    for (int i = 0; i < 2; i++)
        #pragma unroll
        for (int j = 0; j < 4; j++)
            #pragma unroll
            for (int r = 0; r < 4; r++) acc[i][j][r] = 0.f;

    // chunk loader: A 64x32 + B 64x32 -> 1024 float4, 8 per thread.
    // rows 0..63 = A, 64..127 = B (branch uniform per unrolled i).
    auto load_chunk = [&](int c, int s) {
        const float* Ap = A + c * BK;
        const float* Bp = B + c * BK;
        const uint32_t st = sbase + (uint32_t)(s * STAGE_F) * 4u;
        #pragma unroll
        for (int i = 0; i < 8; i++) {
            int idx = tid + i * 128;
            int row = idx >> 3;           // 0..127
            int q   = (idx & 7) * 4;      // 0..28
            const float* src = (row < 64) ? (Ap + (long long)row * lda + q)
                                          : (Bp + (long long)(row - 64) * ldb + q);
            cp_async16(st + (uint32_t)(row * LDP + q) * 4u, src);
        }
    };

    load_chunk(0, 0);
    CP_COMMIT();

    for (int c = 0; c < NC; c++) {
        const int s = c & 1;
        if (c + 1 < NC) {
            load_chunk(c + 1, s ^ 1);
            CP_COMMIT();
            CP_WAIT(1);   // chunk c resident
        } else {
            CP_WAIT(0);
        }
        __syncthreads();

        const float* As = smem + s * STAGE_F + warp_m * 32 * LDP;
        const float* Bs = smem + s * STAGE_F + 64 * LDP + warp_n * 32 * LDP;

        #pragma unroll
        for (int ks = 0; ks < 4; ks++) {
            const int k0 = ks * 8;
            uint32_t af[2][4], bf[4][2];
            #pragma unroll
            for (int im = 0; im < 2; im++) {
                const float* ap = As + (im * 16 + g) * LDP + k0 + tg;
                af[im][0] = f2tf32(ap[0]);
                af[im][1] = f2tf32(ap[8 * LDP]);
                af[im][2] = f2tf32(ap[4]);
                af[im][3] = f2tf32(ap[8 * LDP + 4]);
            }
            #pragma unroll
            for (int in_ = 0; in_ < 4; in_++) {
                const float* bp = Bs + (in_ * 8 + g) * LDP + k0 + tg;
                bf[in_][0] = f2tf32(bp[0]);
                bf[in_][1] = f2tf32(bp[4]);
            }
            #pragma unroll
            for (int im = 0; im < 2; im++)
                #pragma unroll
                for (int in_ = 0; in_ < 4; in_++)
                    MMA_TF32(acc[im][in_], af[im], bf[in_]);
        }
        __syncthreads();   // stage s free before next iteration's prefetch reuses it
    }

    // ---- epilogue: fragments -> gmem (float2 stores) ----
    const int m_base = bm + warp_m * 32;
    const int n_base = bn + warp_n * 32;
    #pragma unroll
    for (int im = 0; im < 2; im++) {
        const int row0 = m_base + im * 16 + g;
        #pragma unroll
        for (int in_ = 0; in_ < 4; in_++) {
            const int col = n_base + in_ * 8 + 2 * tg;
            float bx = 0.f, by = 0.f;
            if (bias) { bx = bias[col]; by = bias[col + 1]; }
            float2 v0 = { alpha * acc[im][in_][0] + bx, alpha * acc[im][in_][1] + by };
            float2 v1 = { alpha * acc[im][in_][2] + bx, alpha * acc[im][in_][3] + by };
            *(float2*)(C + (long long)row0 * ldc + col)       = v0;
            *(float2*)(C + (long long)(row0 + 8) * ldc + col) = v1;
        }
    }
}

// ================= masked softmax (SMEM row cache) =================
__global__ __launch_bounds__(256) void softmax_kernel(
    float* __restrict__ att, const int* __restrict__ mask)
{
    __shared__ float row[SEQ];
    __shared__ float red[8];
    const long long r = blockIdx.x;
    float4* p = (float4*)(att + r * SEQ);
    const int4* m = (const int4*)(mask + r * SEQ);
    const int tid = threadIdx.x;
    const int wid = tid >> 5, lid = tid & 31;

    float mx = -INFINITY;
    for (int i = tid; i < SEQ / 4; i += 256) {
        float4 v = p[i];
        int4 mm = m[i];
        v.x = mm.x ? v.x : -INFINITY;
        v.y = mm.y ? v.y : -INFINITY;
        v.z = mm.z ? v.z : -INFINITY;
        v.w = mm.w ? v.w : -INFINITY;
        ((float4*)row)[i] = v;
        mx = fmaxf(mx, fmaxf(fmaxf(v.x, v.y), fmaxf(v.z, v.w)));
    }
    #pragma unroll
    for (int o = 16; o > 0; o >>= 1) mx = fmaxf(mx, __shfl_xor_sync(0xffffffffu, mx, o));
    if (lid == 0) red[wid] = mx;
    __syncthreads();
    mx = red[lid & 7];
    #pragma unroll
    for (int o = 4; o > 0; o >>= 1) mx = fmaxf(mx, __shfl_xor_sync(0xffffffffu, mx, o));
    mx = __shfl_sync(0xffffffffu, mx, 0);
    __syncthreads();

    float sum = 0.f;
    for (int i = tid; i < SEQ / 4; i += 256) {
        float4 v = ((float4*)row)[i];
        v.x = __expf(v.x - mx);
        v.y = __expf(v.y - mx);
        v.z = __expf(v.z - mx);
        v.w = __expf(v.w - mx);
        ((float4*)row)[i] = v;
        sum += v.x + v.y + v.z + v.w;
    }
    #pragma unroll
    for (int o = 16; o > 0; o >>= 1) sum += __shfl_xor_sync(0xffffffffu, sum, o);
    if (lid == 0) red[wid] = sum;
    __syncthreads();
    sum = red[lid & 7];
    #pragma unroll
    for (int o = 4; o > 0; o >>= 1) sum += __shfl_xor_sync(0xffffffffu, sum, o);
    sum = __shfl_sync(0xffffffffu, sum, 0);
    const float inv = 1.f / sum;
    __syncthreads();

    for (int i = tid; i < SEQ / 4; i += 256) {
        float4 v = ((float4*)row)[i];
        v.x *= inv; v.y *= inv; v.z *= inv; v.w *= inv;
        p[i] = v;
    }
}

// ================= V transpose: Vt[b][e][s] = qkv[b][s][2E+e] =================
__global__ __launch_bounds__(256) void transpose_v(
    const float* __restrict__ qkv, float* __restrict__ vt)
{
    __shared__ float t[32][33];
    const int b = blockIdx.z;
    const int e0 = blockIdx.x * 32, s0 = blockIdx.y * 32;
    const float* base = qkv + (long long)b * SEQ * (3 * EMBED) + 2 * EMBED;
    float* out = vt + (long long)b * EMBED * SEQ;
    const int tx = threadIdx.x, ty = threadIdx.y;
    #pragma unroll
    for (int i = 0; i < 32; i += 8)
        t[ty + i][tx] = base[(long long)(s0 + ty + i) * (3 * EMBED) + e0 + tx];
    __syncthreads();
    #pragma unroll
    for (int i = 0; i < 32; i += 8)
        out[(long long)(e0 + ty + i) * SEQ + s0 + tx] = t[tx][ty + i];
}

// ================= launcher =================
extern "C" void kernel_launch(void* const* d_in, const int* in_sizes, int n_in,
                              void* d_out, int out_size)
{
    const float* X     = (const float*)d_in[0];
    const int*   mask  = (const int*)  d_in[1];
    const float* W_qkv = (const float*)d_in[2];
    const float* b_qkv = (const float*)d_in[3];
    const float* W_out = (const float*)d_in[4];
    const float* b_out = (const float*)d_in[5];
    float* out = (float*)d_out;

    float *qkv, *att, *ctx, *vt;
    cudaGetSymbolAddress((void**)&qkv, g_qkv);
    cudaGetSymbolAddress((void**)&att, g_att);
    cudaGetSymbolAddress((void**)&ctx, g_ctx);
    cudaGetSymbolAddress((void**)&vt,  g_vt);

    cudaFuncSetAttribute(gemm_mma, cudaFuncAttributeMaxDynamicSharedMemorySize, GEMM_DSMEM);

    const float inv_sqrt_e = 1.0f / 32.0f;
    const long long sQKV = (long long)SEQ * 3 * EMBED;
    const long long sATT = (long long)SEQ * SEQ;
    const long long sCTX = (long long)SEQ * EMBED;
    const long long sVT  = (long long)EMBED * SEQ;

    // 1) qkv = X @ W_qkv^T + b_qkv        [8192, 3072], K=1024
    gemm_mma<<<dim3(3 * EMBED / BN, BATCH * SEQ / BM, 1), 128, GEMM_DSMEM>>>(
        X, W_qkv, b_qkv, qkv, EMBED, EMBED, EMBED, 3 * EMBED, 0, 0, 0, 1.0f);

    // transpose V (needs qkv)
    transpose_v<<<dim3(EMBED / 32, SEQ / 32, BATCH), dim3(32, 8)>>>(qkv, vt);

    // 2) att = (q @ k^T) / 32             per batch [2048, 2048], K=1024
    gemm_mma<<<dim3(SEQ / BN, SEQ / BM, BATCH), 128, GEMM_DSMEM>>>(
        qkv, qkv + EMBED, nullptr, att, EMBED, 3 * EMBED, 3 * EMBED, SEQ,
        sQKV, sQKV, sATT, inv_sqrt_e);

    // 3) masked softmax
    softmax_kernel<<<BATCH * SEQ, 256>>>(att, mask);

    // 4) ctx = att @ Vt^T                 per batch [2048, 1024], K=2048
    gemm_mma<<<dim3(EMBED / BN, SEQ / BM, BATCH), 128, GEMM_DSMEM>>>(
        att, vt, nullptr, ctx, SEQ, SEQ, SEQ, EMBED,
        sATT, sVT, sCTX, 1.0f);

    // 5) out = ctx @ W_out^T + b_out      [8192, 1024], K=1024
    gemm_mma<<<dim3(EMBED / BN, BATCH * SEQ / BM, 1), 128, GEMM_DSMEM>>>(
        ctx, W_out, b_out, out, EMBED, EMBED, EMBED, EMBED, 0, 0, 0, 1.0f);
}

// round 14
// speedup vs baseline: 1.5227x; 1.5227x over previous
#include <cuda_runtime.h>
#include <cstdint>

#define EMBED 1024
#define BATCH 4
#define SEQ   2048

// ---- scratch (__device__ globals; no cudaMalloc allowed) ----
__device__ float g_qkv[(size_t)BATCH * SEQ * 3 * EMBED];   // ~100 MB
__device__ float g_att[(size_t)BATCH * SEQ * SEQ];         // ~67 MB
__device__ float g_ctx[(size_t)BATCH * SEQ * EMBED];       // ~33 MB
__device__ float g_vt [(size_t)BATCH * EMBED * SEQ];       // ~33 MB  V transposed
__device__ float g_xr   [(size_t)BATCH * SEQ * EMBED];     // 32 MB  X pre-rounded to tf32
__device__ float g_wqkvr[(size_t)3 * EMBED * EMBED];       // 12 MB  W_qkv pre-rounded
__device__ float g_woutr[(size_t)EMBED * EMBED];           //  4 MB  W_out pre-rounded

// ================= helpers =================
__device__ __forceinline__ void cp_async16(uint32_t smem, const void* gmem) {
    asm volatile("cp.async.cg.shared.global [%0], [%1], 16;" :: "r"(smem), "l"(gmem) : "memory");
}
__device__ __forceinline__ uint32_t smem_u32(const void* p) {
    uint32_t a;
    asm("{ .reg .u64 t; cvta.to.shared.u64 t, %1; cvt.u32.u64 %0, t; }" : "=r"(a) : "l"(p));
    return a;
}
#define CP_COMMIT() asm volatile("cp.async.commit_group;" ::: "memory")
#define CP_WAIT(n)  asm volatile("cp.async.wait_group %0;" :: "n"(n) : "memory")

// Round-to-nearest-even fp32 -> tf32 via integer ops (cvt.rna.tf32 is broken on
// this toolchain). Applied ONCE per tensor element at production time — the GEMM
// mainloop sees pre-rounded data and does no conversion (it was ~40% of issue
// pressure when done per fragment-load). Idempotent.
__device__ __forceinline__ float round_tf32(float x) {
    uint32_t u = __float_as_uint(x);
    return __uint_as_float((u + 0xFFFu + ((u >> 13) & 1u)) & 0xFFFFE000u);
}

// m16n8k8 tf32 mma: D = A*B + D. A row-major(16x8), B col-major(8x8).
// Operands are pre-rounded fp32 bit patterns (valid tf32).
#define MMA_TF32(c, a, b)                                                     \
    asm volatile(                                                             \
        "mma.sync.aligned.m16n8k8.row.col.f32.tf32.tf32.f32 "                 \
        "{%0,%1,%2,%3}, {%4,%5,%6,%7}, {%8,%9}, {%0,%1,%2,%3};"               \
        : "+f"((c)[0]), "+f"((c)[1]), "+f"((c)[2]), "+f"((c)[3])              \
        : "r"((a)[0]), "r"((a)[1]), "r"((a)[2]), "r"((a)[3]),                 \
          "r"((b)[0]), "r"((b)[1]))

// ================= elementwise tf32 pre-round =================
__global__ __launch_bounds__(256) void round_kernel(
    const float* __restrict__ in, float* __restrict__ out, int n4)
{
    int i = blockIdx.x * 256 + threadIdx.x;
    if (i < n4) {
        float4 v = ((const float4*)in)[i];
        v.x = round_tf32(v.x); v.y = round_tf32(v.y);
        v.z = round_tf32(v.z); v.w = round_tf32(v.w);
        ((float4*)out)[i] = v;
    }
}

// ================= tf32 mma.sync NT GEMM =================
// C[m][n] = alpha * sum_k A[m][k]*B[n][k] (+ bias[n]).  A,B K-major fp32
// (pre-rounded to tf32 precision). BM=128, BN=128, BK=32; 8 warps 2(m)x4(n).
// ROUND_OUT: round C to tf32 in the epilogue (for tensors feeding later GEMMs).
static constexpr int BM = 128, BN = 128, BK = 32;
static constexpr int LDP = 36;                       // padded row stride (floats)
static constexpr int STAGE_F = 2 * 128 * LDP;        // A + B per stage (floats)
static constexpr int GEMM_DSMEM = 2 * STAGE_F * 4;   // 73728 bytes

template <bool ROUND_OUT>
__global__ __launch_bounds__(256, 2) void gemm_mma(
    const float* __restrict__ A, const float* __restrict__ B,
    const float* __restrict__ bias, float* __restrict__ C,
    int K, int lda, int ldb, int ldc,
    long long sA, long long sB, long long sC, float alpha)
{
    extern __shared__ float smem[];

    const int tid = threadIdx.x;
    const int wid = tid >> 5;
    const int lid = tid & 31;
    const int g   = lid >> 2;     // 0..7
    const int tg  = lid & 3;      // 0..3
    const int warp_m = wid >> 2;  // 0..1  -> 64 rows each
    const int warp_n = wid & 3;   // 0..3  -> 32 cols each

    const int bm = blockIdx.y * BM;
    const int bn = blockIdx.x * BN;

    A += blockIdx.z * sA + (long long)bm * lda;
    B += blockIdx.z * sB + (long long)bn * ldb;
    C += blockIdx.z * sC;

    const uint32_t sbase = smem_u32(smem);
    const int NC = K / BK;

    float acc[4][4][4];
    #pragma unroll
    for (int i = 0; i < 4; i++)
        #pragma unroll
        for (int j = 0; j < 4; j++)
            #pragma unroll
            for (int r = 0; r < 4; r++) acc[i][j][r] = 0.f;

    // chunk loader: A 128x32 + B 128x32, rows padded to LDP floats
    auto load_chunk = [&](int c, int s) {
        const float* Ap = A + c * BK;
        const float* Bp = B + c * BK;
        const uint32_t sa = sbase + (uint32_t)(s * STAGE_F) * 4u;
        const uint32_t sb = sa + 128u * LDP * 4u;
        #pragma unroll
        for (int i = 0; i < 4; i++) {
            int idx = tid + i * 256;
            int row = idx >> 3;
            int q   = (idx & 7) * 4;
            uint32_t off = (uint32_t)(row * LDP + q) * 4u;
            cp_async16(sa + off, Ap + (long long)row * lda + q);
            cp_async16(sb + off, Bp + (long long)row * ldb + q);
        }
    };

    load_chunk(0, 0);
    CP_COMMIT();

    for (int c = 0; c < NC; c++) {
        const int s = c & 1;
        if (c + 1 < NC) {
            load_chunk(c + 1, s ^ 1);
            CP_COMMIT();
            CP_WAIT(1);   // chunk c resident
        } else {
            CP_WAIT(0);
        }
        __syncthreads();

        const float* As = smem + s * STAGE_F + warp_m * 64 * LDP;
        const float* Bs = smem + s * STAGE_F + 128 * LDP + warp_n * 32 * LDP;

        #pragma unroll
        for (int ks = 0; ks < 4; ks++) {
            const int k0 = ks * 8;
            uint32_t af[4][4], bf[4][2];
            #pragma unroll
            for (int im = 0; im < 4; im++) {
                const float* ap = As + (im * 16 + g) * LDP + k0 + tg;
                af[im][0] = __float_as_uint(ap[0]);
                af[im][1] = __float_as_uint(ap[8 * LDP]);
                af[im][2] = __float_as_uint(ap[4]);
                af[im][3] = __float_as_uint(ap[8 * LDP + 4]);
            }
            #pragma unroll
            for (int in_ = 0; in_ < 4; in_++) {
                const float* bp = Bs + (in_ * 8 + g) * LDP + k0 + tg;
                bf[in_][0] = __float_as_uint(bp[0]);
                bf[in_][1] = __float_as_uint(bp[4]);
            }
            #pragma unroll
            for (int im = 0; im < 4; im++)
                #pragma unroll
                for (int in_ = 0; in_ < 4; in_++)
                    MMA_TF32(acc[im][in_], af[im], bf[in_]);
        }
        __syncthreads();   // stage s free before next iteration's prefetch reuses it
    }

    // ---- epilogue: fragments -> gmem (float2 stores) ----
    const int m_base = bm + warp_m * 64;
    const int n_base = bn + warp_n * 32;
    #pragma unroll
    for (int im = 0; im < 4; im++) {
        const int row0 = m_base + im * 16 + g;
        #pragma unroll
        for (int in_ = 0; in_ < 4; in_++) {
            const int col = n_base + in_ * 8 + 2 * tg;
            float bx = 0.f, by = 0.f;
            if (bias) { bx = bias[col]; by = bias[col + 1]; }
            float2 v0 = { alpha * acc[im][in_][0] + bx, alpha * acc[im][in_][1] + by };
            float2 v1 = { alpha * acc[im][in_][2] + bx, alpha * acc[im][in_][3] + by };
            if (ROUND_OUT) {
                v0.x = round_tf32(v0.x); v0.y = round_tf32(v0.y);
                v1.x = round_tf32(v1.x); v1.y = round_tf32(v1.y);
            }
            *(float2*)(C + (long long)row0 * ldc + col)       = v0;
            *(float2*)(C + (long long)(row0 + 8) * ldc + col) = v1;
        }
    }
}

// ================= masked softmax (SMEM row cache) =================
// Output rounded to tf32 precision (feeds GEMM4 as A operand).
__global__ __launch_bounds__(256) void softmax_kernel(
    float* __restrict__ att, const int* __restrict__ mask)
{
    __shared__ float row[SEQ];
    __shared__ float red[8];
    const long long r = blockIdx.x;
    float4* p = (float4*)(att + r * SEQ);
    const int4* m = (const int4*)(mask + r * SEQ);
    const int tid = threadIdx.x;
    const int wid = tid >> 5, lid = tid & 31;

    float mx = -INFINITY;
    for (int i = tid; i < SEQ / 4; i += 256) {
        float4 v = p[i];
        int4 mm = m[i];
        v.x = mm.x ? v.x : -INFINITY;
        v.y = mm.y ? v.y : -INFINITY;
        v.z = mm.z ? v.z : -INFINITY;
        v.w = mm.w ? v.w : -INFINITY;
        ((float4*)row)[i] = v;
        mx = fmaxf(mx, fmaxf(fmaxf(v.x, v.y), fmaxf(v.z, v.w)));
    }
    #pragma unroll
    for (int o = 16; o > 0; o >>= 1) mx = fmaxf(mx, __shfl_xor_sync(0xffffffffu, mx, o));
    if (lid == 0) red[wid] = mx;
    __syncthreads();
    mx = red[lid & 7];
    #pragma unroll
    for (int o = 4; o > 0; o >>= 1) mx = fmaxf(mx, __shfl_xor_sync(0xffffffffu, mx, o));
    mx = __shfl_sync(0xffffffffu, mx, 0);
    __syncthreads();

    float sum = 0.f;
    for (int i = tid; i < SEQ / 4; i += 256) {
        float4 v = ((float4*)row)[i];
        v.x = __expf(v.x - mx);
        v.y = __expf(v.y - mx);
        v.z = __expf(v.z - mx);
        v.w = __expf(v.w - mx);
        ((float4*)row)[i] = v;
        sum += v.x + v.y + v.z + v.w;
    }
    #pragma unroll
    for (int o = 16; o > 0; o >>= 1) sum += __shfl_xor_sync(0xffffffffu, sum, o);
    if (lid == 0) red[wid] = sum;
    __syncthreads();
    sum = red[lid & 7];
    #pragma unroll
    for (int o = 4; o > 0; o >>= 1) sum += __shfl_xor_sync(0xffffffffu, sum, o);
    sum = __shfl_sync(0xffffffffu, sum, 0);
    const float inv = 1.f / sum;
    __syncthreads();

    for (int i = tid; i < SEQ / 4; i += 256) {
        float4 v = ((float4*)row)[i];
        v.x = round_tf32(v.x * inv);
        v.y = round_tf32(v.y * inv);
        v.z = round_tf32(v.z * inv);
        v.w = round_tf32(v.w * inv);
        p[i] = v;
    }
}

// ================= V transpose: Vt[b][e][s] = qkv[b][s][2E+e] =================
// qkv is already tf32-rounded by GEMM1's epilogue; transpose preserves it.
__global__ __launch_bounds__(256) void transpose_v(
    const float* __restrict__ qkv, float* __restrict__ vt)
{
    __shared__ float t[32][33];
    const int b = blockIdx.z;
    const int e0 = blockIdx.x * 32, s0 = blockIdx.y * 32;
    const float* base = qkv + (long long)b * SEQ * (3 * EMBED) + 2 * EMBED;
    float* out = vt + (long long)b * EMBED * SEQ;
    const int tx = threadIdx.x, ty = threadIdx.y;
    #pragma unroll
    for (int i = 0; i < 32; i += 8)
        t[ty + i][tx] = base[(long long)(s0 + ty + i) * (3 * EMBED) + e0 + tx];
    __syncthreads();
    #pragma unroll
    for (int i = 0; i < 32; i += 8)
        out[(long long)(e0 + ty + i) * SEQ + s0 + tx] = t[tx][ty + i];
}

// ================= launcher =================
extern "C" void kernel_launch(void* const* d_in, const int* in_sizes, int n_in,
                              void* d_out, int out_size)
{
    const float* X     = (const float*)d_in[0];
    const int*   mask  = (const int*)  d_in[1];
    const float* W_qkv = (const float*)d_in[2];
    const float* b_qkv = (const float*)d_in[3];
    const float* W_out = (const float*)d_in[4];
    const float* b_out = (const float*)d_in[5];
    float* out = (float*)d_out;

    float *qkv, *att, *ctx, *vt, *xr, *wqkvr, *woutr;
    cudaGetSymbolAddress((void**)&qkv,   g_qkv);
    cudaGetSymbolAddress((void**)&att,   g_att);
    cudaGetSymbolAddress((void**)&ctx,   g_ctx);
    cudaGetSymbolAddress((void**)&vt,    g_vt);
    cudaGetSymbolAddress((void**)&xr,    g_xr);
    cudaGetSymbolAddress((void**)&wqkvr, g_wqkvr);
    cudaGetSymbolAddress((void**)&woutr, g_woutr);

    cudaFuncSetAttribute(gemm_mma<true>,  cudaFuncAttributeMaxDynamicSharedMemorySize, GEMM_DSMEM);
    cudaFuncSetAttribute(gemm_mma<false>, cudaFuncAttributeMaxDynamicSharedMemorySize, GEMM_DSMEM);

    const float inv_sqrt_e = 1.0f / 32.0f;
    const long long sQKV = (long long)SEQ * 3 * EMBED;
    const long long sATT = (long long)SEQ * SEQ;
    const long long sCTX = (long long)SEQ * EMBED;
    const long long sVT  = (long long)EMBED * SEQ;

    // 0) pre-round MMA operand tensors to tf32 precision (one-time, ~12us)
    {
        int nX = BATCH * SEQ * EMBED / 4;
        int nWq = 3 * EMBED * EMBED / 4;
        int nWo = EMBED * EMBED / 4;
        round_kernel<<<(nX + 255) / 256, 256>>>(X, xr, nX);
        round_kernel<<<(nWq + 255) / 256, 256>>>(W_qkv, wqkvr, nWq);
        round_kernel<<<(nWo + 255) / 256, 256>>>(W_out, woutr, nWo);
    }

    // 1) qkv = Xr @ Wqkvr^T + b_qkv       [8192, 3072], K=1024; round output
    gemm_mma<true><<<dim3(3 * EMBED / BN, BATCH * SEQ / BM, 1), 256, GEMM_DSMEM>>>(
        xr, wqkvr, b_qkv, qkv, EMBED, EMBED, EMBED, 3 * EMBED, 0, 0, 0, 1.0f);

    // transpose V (qkv already rounded)
    transpose_v<<<dim3(EMBED / 32, SEQ / 32, BATCH), dim3(32, 8)>>>(qkv, vt);

    // 2) att = (q @ k^T) / 32             per batch [2048, 2048], K=1024
    //    (softmax rounds att afterwards; no round here)
    gemm_mma<false><<<dim3(SEQ / BN, SEQ / BM, BATCH), 256, GEMM_DSMEM>>>(
        qkv, qkv + EMBED, nullptr, att, EMBED, 3 * EMBED, 3 * EMBED, SEQ,
        sQKV, sQKV, sATT, inv_sqrt_e);

    // 3) masked softmax (rounds output to tf32)
    softmax_kernel<<<BATCH * SEQ, 256>>>(att, mask);

    // 4) ctx = att @ Vt^T                 per batch [2048, 1024], K=2048; round output
    gemm_mma<true><<<dim3(EMBED / BN, SEQ / BM, BATCH), 256, GEMM_DSMEM>>>(
        att, vt, nullptr, ctx, SEQ, SEQ, SEQ, EMBED,
        sATT, sVT, sCTX, 1.0f);

    // 5) out = ctx @ Woutr^T + b_out      [8192, 1024], K=1024; final, no round
    gemm_mma<false><<<dim3(EMBED / BN, BATCH * SEQ / BM, 1), 256, GEMM_DSMEM>>>(
        ctx, woutr, b_out, out, EMBED, EMBED, EMBED, EMBED, 0, 0, 0, 1.0f);
}